// round 16
// baseline (speedup 1.0000x reference)
#include <cuda_runtime.h>
#include <cuda_fp16.h>

#define MAXN 100000
#define MAXE 1600000
#define C 64
#define SCANB 256
#define MAXBLK 512

// ---------------- scratch (static device globals; no allocation) ------------
__device__ int    g_count[MAXN];
__device__ int    g_blkagg[MAXBLK];   // lookback aggregates (value+1; 0 = not ready)
__device__ int    g_off[MAXN + 1];
__device__ int    g_cur[MAXN];
__device__ int    g_csr[MAXE + 16];
__device__ float  g_dinv[MAXN];
__device__ float  g_agg[MAXN * C];   // also reused: g_p = g_agg, g_s = g_agg+MAXN
__device__ float  g_h1[MAXN * C];
__device__ __half g_xh[MAXN * C];    // fp16 gather mirror of x
__device__ __half g_h1h[MAXN * C];   // fp16 gather mirror of h1

// ---------------- packed f32x2 helpers --------------------------------------
#define FMA2(d, a, b) \
    asm("fma.rn.f32x2 %0, %1, %2, %0;" : "+l"(d) : "l"(a), "l"(b))
#define UNPACK2(lo, hi, v) \
    asm("mov.b64 {%0, %1}, %2;" : "=f"(lo), "=f"(hi) : "l"(v))

__device__ __forceinline__ float4 h4_to_f4(uint2 u) {
    float2 f0 = __half22float2(*(__half2*)&u.x);
    float2 f1 = __half22float2(*(__half2*)&u.y);
    return make_float4(f0.x, f0.y, f1.x, f1.y);
}

// ---------------- CSR build + x->fp16 (fused: same grid) --------------------
__global__ void k_hist(const int* __restrict__ row, int e,
                       const float* __restrict__ x, int total4) {
    int i = blockIdx.x * blockDim.x + threadIdx.x;
    if (i < e) atomicAdd(&g_count[row[i]], 1);
    if (i < total4) {
        float4 v = ((const float4*)x)[i];
        __half2 a = __floats2half2_rn(v.x, v.y);
        __half2 b = __floats2half2_rn(v.z, v.w);
        ((uint2*)g_xh)[i] = make_uint2(*(unsigned*)&a, *(unsigned*)&b);
    }
}

// single-pass scan with decoupled lookback.
__global__ void k_scan(int n, int e) {
    __shared__ int sh[SCANB];
    __shared__ int s_prefix;
    int t   = threadIdx.x;
    int bid = blockIdx.x;
    int i   = bid * SCANB + t;
    int cnt = (i < n) ? g_count[i] : 0;
    sh[t] = cnt;
    __syncthreads();
    #pragma unroll
    for (int off = 1; off < SCANB; off <<= 1) {
        int add = (t >= off) ? sh[t - off] : 0;
        __syncthreads();
        sh[t] += add;
        __syncthreads();
    }
    int incl = sh[t];
    if (t == SCANB - 1) {
        __threadfence();
        atomicExch(&g_blkagg[bid], incl + 1);   // publish block total (+1 flag)
    }
    if (t < 32) {
        int acc = 0;
        for (int idx = t; idx < bid; idx += 32) {
            int v = *(volatile int*)&g_blkagg[idx];
            while (v == 0) v = *(volatile int*)&g_blkagg[idx];
            acc += v - 1;
        }
        #pragma unroll
        for (int o = 16; o; o >>= 1) acc += __shfl_xor_sync(0xffffffffu, acc, o);
        if (t == 0) s_prefix = acc;
    }
    __syncthreads();
    if (i < n) {
        int off = s_prefix + incl - cnt;
        g_off[i]  = off;
        g_cur[i]  = off;
        g_dinv[i] = 1.0f / (float)(cnt > 1 ? cnt : 1);
    }
    if (i == 0) g_off[n] = e;
}

__global__ void k_fill(const int* __restrict__ row, const int* __restrict__ col,
                       int e) {
    int i = blockIdx.x * blockDim.x + threadIdx.x;
    if (i < e) {
        int p = atomicAdd(&g_cur[row[i]], 1);
        g_csr[p] = col[i];
    }
}

// ---------------- mean aggregation: fp16 gather, fp32 accumulate ------------
// TWO nodes per warp, 16 lanes x uint2 (4 halves = 8B) per row, 4-deep MLP,
// float4 accumulator, <=32 regs (launch_bounds(256,8) -> 64-warp ceiling).
// srcSel: 0 -> g_xh, 1 -> g_h1h.
__global__ __launch_bounds__(256, 8) void k_agg(int srcSel, int n) {
    int gw   = (blockIdx.x * blockDim.x + threadIdx.x) >> 5;
    int lane = threadIdx.x & 31;
    int half = lane >> 4;
    int sub  = lane & 15;
    int node = gw * 2 + half;
    const uint2* __restrict__ src =
        (const uint2*)((srcSel == 0) ? g_xh : g_h1h);

    int s = 0, e0 = 0;
    if (node < n) { s = g_off[node]; e0 = g_off[node + 1]; }

    float4 acc = make_float4(0.f, 0.f, 0.f, 0.f);
    int j = s;

    for (; j + 3 < e0; j += 4) {
        int c0 = g_csr[j], c1 = g_csr[j + 1], c2 = g_csr[j + 2], c3 = g_csr[j + 3];
        uint2 u0 = src[(size_t)c0 * 16 + sub];
        uint2 u1 = src[(size_t)c1 * 16 + sub];
        uint2 u2 = src[(size_t)c2 * 16 + sub];
        uint2 u3 = src[(size_t)c3 * 16 + sub];
        float4 v0 = h4_to_f4(u0);
        float4 v1 = h4_to_f4(u1);
        float4 v2 = h4_to_f4(u2);
        float4 v3 = h4_to_f4(u3);
        float4 s01, s23;
        s01.x = v0.x + v1.x; s01.y = v0.y + v1.y;
        s01.z = v0.z + v1.z; s01.w = v0.w + v1.w;
        s23.x = v2.x + v3.x; s23.y = v2.y + v3.y;
        s23.z = v2.z + v3.z; s23.w = v2.w + v3.w;
        acc.x += s01.x + s23.x; acc.y += s01.y + s23.y;
        acc.z += s01.z + s23.z; acc.w += s01.w + s23.w;
    }
    for (; j < e0; j++) {
        float4 v = h4_to_f4(src[(size_t)g_csr[j] * 16 + sub]);
        acc.x += v.x; acc.y += v.y; acc.z += v.z; acc.w += v.w;
    }
    if (node < n) {
        float d = g_dinv[node];
        float4 o;
        o.x = acc.x * d; o.y = acc.y * d; o.z = acc.z * d; o.w = acc.w * d;
        *(float4*)(g_agg + (size_t)node * C + (sub << 2)) = o;
    }
}

// ---------------- GEMM: relu( concat(X, AGG)[n,128] @ W^T + b ) -------------
// Tile: 128 nodes x 64 cols per block, 128 threads, k chunked by 32.
// 8x8 per-thread tile via packed f32x2 FFMA, register-pipelined chunks.
// fuseMode 0: write rows to g_h1 (fp32) + g_h1h (fp16 gather mirror).
// fuseMode 1: layer-3 fusion (project onto W3 halves, emit g_s/g_p scalars).
#define NT2 128
#define KC  32

__global__ __launch_bounds__(128, 4) void k_gemm(
    const float* __restrict__ Xin, int srcSel,
    const float* __restrict__ W, const float* __restrict__ B,
    int n, int do_relu, int fuseMode, const float* __restrict__ W3)
{
    __shared__ float Hs[KC][NT2];      // transposed H chunk: Hs[kk][node]
    __shared__ float Wd[KC][128];      // duplicated W chunk

    const float* __restrict__ Xs = (srcSel == 0) ? Xin : g_h1;

    int t  = threadIdx.x;              // 0..127
    int nb = blockIdx.x * NT2;
    int tx = t & 15;      // node-group: 16 groups x 8 nodes
    int ty = t >> 4;      // col-group:   8 groups x 8 cols

    unsigned long long acc[4][8];
    #pragma unroll
    for (int i = 0; i < 4; i++)
        #pragma unroll
        for (int j = 0; j < 8; j++) acc[i][j] = 0ull;

    int nglob = nb + t;          // H staging: one node per thread
    int colw  = t >> 1;          // W staging: col 0..63
    int q     = t & 1;           // half of the 32-k chunk (16 k each)

    float4 hreg[8];
    float4 wreg[4];

    // preload chunk 0
    {
        const float4* srow = (const float4*)(Xs + (size_t)nglob * C);
        #pragma unroll
        for (int i = 0; i < 8; i++)
            hreg[i] = (nglob < n) ? srow[i] : make_float4(0.f, 0.f, 0.f, 0.f);
        #pragma unroll
        for (int i = 0; i < 4; i++)
            wreg[i] = *(const float4*)(W + colw * 128 + q * 16 + i * 4);
    }

    for (int c = 0; c < 4; c++) {
        #pragma unroll
        for (int i = 0; i < 8; i++) {
            int kk = i * 4;
            Hs[kk + 0][t] = hreg[i].x;
            Hs[kk + 1][t] = hreg[i].y;
            Hs[kk + 2][t] = hreg[i].z;
            Hs[kk + 3][t] = hreg[i].w;
        }
        #pragma unroll
        for (int i = 0; i < 4; i++) {
            int kk = q * 16 + i * 4;
            Wd[kk + 0][2 * colw] = wreg[i].x;  Wd[kk + 0][2 * colw + 1] = wreg[i].x;
            Wd[kk + 1][2 * colw] = wreg[i].y;  Wd[kk + 1][2 * colw + 1] = wreg[i].y;
            Wd[kk + 2][2 * colw] = wreg[i].z;  Wd[kk + 2][2 * colw + 1] = wreg[i].z;
            Wd[kk + 3][2 * colw] = wreg[i].w;  Wd[kk + 3][2 * colw + 1] = wreg[i].w;
        }
        __syncthreads();

        if (c < 3) {
            int cn = c + 1;
            const float* src = (cn < 2) ? Xs : g_agg;
            int koff = (cn & 1) * 32;
            int kb   = cn * 32;
            const float4* srow = (const float4*)(src + (size_t)nglob * C + koff);
            #pragma unroll
            for (int i = 0; i < 8; i++)
                hreg[i] = (nglob < n) ? srow[i] : make_float4(0.f, 0.f, 0.f, 0.f);
            #pragma unroll
            for (int i = 0; i < 4; i++)
                wreg[i] = *(const float4*)(W + colw * 128 + kb + q * 16 + i * 4);
        }

        #pragma unroll 8
        for (int kk = 0; kk < KC; kk++) {
            ulonglong2 aA = *(const ulonglong2*)&Hs[kk][tx * 8];
            ulonglong2 aB = *(const ulonglong2*)&Hs[kk][tx * 8 + 4];
            const ulonglong2* bp = (const ulonglong2*)&Wd[kk][ty * 16];
            ulonglong2 b01 = bp[0], b23 = bp[1], b45 = bp[2], b67 = bp[3];
            unsigned long long bb[8] = {b01.x, b01.y, b23.x, b23.y,
                                        b45.x, b45.y, b67.x, b67.y};
            #pragma unroll
            for (int j = 0; j < 8; j++) {
                FMA2(acc[0][j], aA.x, bb[j]);
                FMA2(acc[1][j], aA.y, bb[j]);
                FMA2(acc[2][j], aB.x, bb[j]);
                FMA2(acc[3][j], aB.y, bb[j]);
            }
        }
        __syncthreads();
    }

    float4 bb0 = *(const float4*)(B + ty * 8);
    float4 bb1 = *(const float4*)(B + ty * 8 + 4);
    float bias[8] = {bb0.x, bb0.y, bb0.z, bb0.w, bb1.x, bb1.y, bb1.z, bb1.w};

    if (fuseMode == 0) {
        #pragma unroll
        for (int i2 = 0; i2 < 4; i2++) {
            float lo[8], hi[8];
            #pragma unroll
            for (int j = 0; j < 8; j++) {
                UNPACK2(lo[j], hi[j], acc[i2][j]);
                lo[j] += bias[j]; hi[j] += bias[j];
                if (do_relu) { lo[j] = fmaxf(lo[j], 0.f); hi[j] = fmaxf(hi[j], 0.f); }
            }
            int n0 = nb + tx * 8 + i2 * 2;
            if (n0 < n) {
                float4* o = (float4*)(g_h1 + (size_t)n0 * C + ty * 8);
                o[0] = make_float4(lo[0], lo[1], lo[2], lo[3]);
                o[1] = make_float4(lo[4], lo[5], lo[6], lo[7]);
                __half2 p0 = __floats2half2_rn(lo[0], lo[1]);
                __half2 p1 = __floats2half2_rn(lo[2], lo[3]);
                __half2 p2 = __floats2half2_rn(lo[4], lo[5]);
                __half2 p3 = __floats2half2_rn(lo[6], lo[7]);
                *(uint4*)(g_h1h + (size_t)n0 * C + ty * 8) =
                    make_uint4(*(unsigned*)&p0, *(unsigned*)&p1,
                               *(unsigned*)&p2, *(unsigned*)&p3);
            }
            if (n0 + 1 < n) {
                float4* o = (float4*)(g_h1 + (size_t)(n0 + 1) * C + ty * 8);
                o[0] = make_float4(hi[0], hi[1], hi[2], hi[3]);
                o[1] = make_float4(hi[4], hi[5], hi[6], hi[7]);
                __half2 p0 = __floats2half2_rn(hi[0], hi[1]);
                __half2 p1 = __floats2half2_rn(hi[2], hi[3]);
                __half2 p2 = __floats2half2_rn(hi[4], hi[5]);
                __half2 p3 = __floats2half2_rn(hi[6], hi[7]);
                *(uint4*)(g_h1h + (size_t)(n0 + 1) * C + ty * 8) =
                    make_uint4(*(unsigned*)&p0, *(unsigned*)&p1,
                               *(unsigned*)&p2, *(unsigned*)&p3);
            }
        }
    } else {
        float w3s[8], w3p[8];
        #pragma unroll
        for (int j = 0; j < 8; j++) {
            w3s[j] = W3[ty * 8 + j];
            w3p[j] = W3[64 + ty * 8 + j];
        }
        float* Ps = &Hs[0][0];          // [8][128]
        float* Ss = &Hs[0][0] + 1024;   // [8][128]

        #pragma unroll
        for (int i2 = 0; i2 < 4; i2++) {
            float lo[8], hi[8];
            float slo = 0.f, plo = 0.f, shi = 0.f, phi = 0.f;
            #pragma unroll
            for (int j = 0; j < 8; j++) {
                UNPACK2(lo[j], hi[j], acc[i2][j]);
                lo[j] = fmaxf(lo[j] + bias[j], 0.f);
                hi[j] = fmaxf(hi[j] + bias[j], 0.f);
                slo += lo[j] * w3s[j];  plo += lo[j] * w3p[j];
                shi += hi[j] * w3s[j];  phi += hi[j] * w3p[j];
            }
            int nl = tx * 8 + i2 * 2;
            Ss[ty * 128 + nl]     = slo;  Ps[ty * 128 + nl]     = plo;
            Ss[ty * 128 + nl + 1] = shi;  Ps[ty * 128 + nl + 1] = phi;
        }
        __syncthreads();
        int node = nb + t;
        if (node < n) {
            float s = 0.f, p = 0.f;
            #pragma unroll
            for (int g = 0; g < 8; g++) {
                s += Ss[g * 128 + t];
                p += Ps[g * 128 + t];
            }
            g_agg[MAXN + node] = s;   // g_s (bias b3 added in k_out)
            g_agg[node]        = p;   // g_p
        }
    }
}

// scalar aggregation + combine: out[i] = s[i] + b3 + dinv[i] * sum p[nbrs].
// Tail also resets g_count/g_blkagg for the next replay (consumed only by
// k_hist/k_scan, which run before this kernel in every invocation).
__global__ void k_out(float* __restrict__ OUT, const float* __restrict__ B3, int n) {
    int i = blockIdx.x * blockDim.x + threadIdx.x;
    if (i < MAXBLK) g_blkagg[i] = 0;
    if (i >= n) return;
    g_count[i] = 0;
    int s = g_off[i], e = g_off[i + 1];
    float a0 = 0.f, a1 = 0.f, a2 = 0.f, a3 = 0.f;
    float a4 = 0.f, a5 = 0.f, a6 = 0.f, a7 = 0.f;
    int j = s;
    for (; j + 7 < e; j += 8) {
        a0 += g_agg[g_csr[j]];
        a1 += g_agg[g_csr[j + 1]];
        a2 += g_agg[g_csr[j + 2]];
        a3 += g_agg[g_csr[j + 3]];
        a4 += g_agg[g_csr[j + 4]];
        a5 += g_agg[g_csr[j + 5]];
        a6 += g_agg[g_csr[j + 6]];
        a7 += g_agg[g_csr[j + 7]];
    }
    for (; j < e; j++) a0 += g_agg[g_csr[j]];
    float acc = ((a0 + a1) + (a2 + a3)) + ((a4 + a5) + (a6 + a7));
    OUT[i] = g_agg[MAXN + i] + B3[0] + acc * g_dinv[i];
}

// ---------------- driver ----------------------------------------------------
extern "C" void kernel_launch(void* const* d_in, const int* in_sizes, int n_in,
                              void* d_out, int out_size)
{
    const float* x  = (const float*)d_in[0];
    const int*   ei = (const int*)  d_in[1];
    const float* W1 = (const float*)d_in[2];
    const float* b1 = (const float*)d_in[3];
    const float* W2 = (const float*)d_in[4];
    const float* b2 = (const float*)d_in[5];
    const float* W3 = (const float*)d_in[6];
    const float* b3 = (const float*)d_in[7];
    float* out = (float*)d_out;

    int n = in_sizes[0] / C;     // 100000
    int e = in_sizes[1] / 2;     // 1600000
    const int* row = ei;
    const int* col = ei + e;

    int scanBlk = (n + SCANB - 1) / SCANB;   // 391 <= MAXBLK

    // CSR build + x->fp16 (fused), 3 launches; counter resets in k_out tail
    k_hist<<<(e + 255) / 256, 256>>>(row, e, x, n * 16);   // launch 0
    k_scan<<<scanBlk, SCANB>>>(n, e);                      // launch 1
    k_fill<<<(e + 255) / 256, 256>>>(row, col, e);         // launch 2

    int aggBlocks  = ((n + 1) / 2 + 7) / 8;  // 2 nodes/warp, 8 warps/block
    int gemmBlocks = (n + NT2 - 1) / NT2;    // 782
    int tpnBlocks  = (n + 255) / 256;

    // layer 1: x -> h1 (+ fp16 mirror)
    k_agg <<<aggBlocks, 256>>>(0, n);                      // launch 3
    k_gemm<<<gemmBlocks, 128>>>(x, 0, W1, b1, n, 1, 0, nullptr);   // launch 4
    // layer 2 + 3: h1 -> (s,p) scalars (h2 never materialized)
    k_agg <<<aggBlocks, 256>>>(1, n);                      // launch 5
    k_gemm<<<gemmBlocks, 128>>>(nullptr, 1, W2, b2, n, 1, 1, W3);  // launch 6
    // layer 3 scalar aggregation (+ counter resets for next replay)
    k_out <<<tpnBlocks, 256>>>(out, b3, n);                // launch 7
}

// round 17
// speedup vs baseline: 1.0247x; 1.0247x over previous
#include <cuda_runtime.h>
#include <cuda_fp16.h>

#define MAXN 100000
#define MAXE 1600000
#define C 64
#define SCANB 256
#define MAXBLK 512

// ---------------- scratch (static device globals; no allocation) ------------
__device__ int    g_count[MAXN];
__device__ int    g_blkagg[MAXBLK];   // lookback aggregates (value+1; 0 = not ready)
__device__ int    g_off[MAXN + 1];
__device__ int    g_cur[MAXN];
__device__ int    g_csr[MAXE + 16];
__device__ float  g_dinv[MAXN];
__device__ float  g_agg[MAXN * C];   // also reused: g_p = g_agg, g_s = g_agg+MAXN
__device__ __half g_xh[MAXN * C];    // fp16 gather mirror of x
__device__ __half g_h1h[MAXN * C];   // h1 lives ONLY in fp16 (sole copy)

// ---------------- packed f32x2 helpers --------------------------------------
#define FMA2(d, a, b) \
    asm("fma.rn.f32x2 %0, %1, %2, %0;" : "+l"(d) : "l"(a), "l"(b))
#define UNPACK2(lo, hi, v) \
    asm("mov.b64 {%0, %1}, %2;" : "=f"(lo), "=f"(hi) : "l"(v))

__device__ __forceinline__ float4 h4_to_f4(uint2 u) {
    float2 f0 = __half22float2(*(__half2*)&u.x);
    float2 f1 = __half22float2(*(__half2*)&u.y);
    return make_float4(f0.x, f0.y, f1.x, f1.y);
}

// ---------------- CSR build + x->fp16 (fused: same grid) --------------------
__global__ void k_hist(const int* __restrict__ row, int e,
                       const float* __restrict__ x, int total4) {
    int i = blockIdx.x * blockDim.x + threadIdx.x;
    if (i < e) atomicAdd(&g_count[row[i]], 1);
    if (i < total4) {
        float4 v = ((const float4*)x)[i];
        __half2 a = __floats2half2_rn(v.x, v.y);
        __half2 b = __floats2half2_rn(v.z, v.w);
        ((uint2*)g_xh)[i] = make_uint2(*(unsigned*)&a, *(unsigned*)&b);
    }
}

// single-pass scan with decoupled lookback.
__global__ void k_scan(int n, int e) {
    __shared__ int sh[SCANB];
    __shared__ int s_prefix;
    int t   = threadIdx.x;
    int bid = blockIdx.x;
    int i   = bid * SCANB + t;
    int cnt = (i < n) ? g_count[i] : 0;
    sh[t] = cnt;
    __syncthreads();
    #pragma unroll
    for (int off = 1; off < SCANB; off <<= 1) {
        int add = (t >= off) ? sh[t - off] : 0;
        __syncthreads();
        sh[t] += add;
        __syncthreads();
    }
    int incl = sh[t];
    if (t == SCANB - 1) {
        __threadfence();
        atomicExch(&g_blkagg[bid], incl + 1);   // publish block total (+1 flag)
    }
    if (t < 32) {
        int acc = 0;
        for (int idx = t; idx < bid; idx += 32) {
            int v = *(volatile int*)&g_blkagg[idx];
            while (v == 0) v = *(volatile int*)&g_blkagg[idx];
            acc += v - 1;
        }
        #pragma unroll
        for (int o = 16; o; o >>= 1) acc += __shfl_xor_sync(0xffffffffu, acc, o);
        if (t == 0) s_prefix = acc;
    }
    __syncthreads();
    if (i < n) {
        int off = s_prefix + incl - cnt;
        g_off[i]  = off;
        g_cur[i]  = off;
        g_dinv[i] = 1.0f / (float)(cnt > 1 ? cnt : 1);
    }
    if (i == 0) g_off[n] = e;
}

__global__ void k_fill(const int* __restrict__ row, const int* __restrict__ col,
                       int e) {
    int i = blockIdx.x * blockDim.x + threadIdx.x;
    if (i < e) {
        int p = atomicAdd(&g_cur[row[i]], 1);
        g_csr[p] = col[i];
    }
}

// ---------------- mean aggregation: fp16 gather, fp32 accumulate ------------
// TWO nodes per warp, 16 lanes x uint2 (4 halves = 8B) per row, 4-deep MLP,
// float4 accumulator, <=32 regs (launch_bounds(256,8) -> 64-warp ceiling).
// srcSel: 0 -> g_xh, 1 -> g_h1h.
__global__ __launch_bounds__(256, 8) void k_agg(int srcSel, int n) {
    int gw   = (blockIdx.x * blockDim.x + threadIdx.x) >> 5;
    int lane = threadIdx.x & 31;
    int half = lane >> 4;
    int sub  = lane & 15;
    int node = gw * 2 + half;
    const uint2* __restrict__ src =
        (const uint2*)((srcSel == 0) ? g_xh : g_h1h);

    int s = 0, e0 = 0;
    if (node < n) { s = g_off[node]; e0 = g_off[node + 1]; }

    float4 acc = make_float4(0.f, 0.f, 0.f, 0.f);
    int j = s;

    for (; j + 3 < e0; j += 4) {
        int c0 = g_csr[j], c1 = g_csr[j + 1], c2 = g_csr[j + 2], c3 = g_csr[j + 3];
        uint2 u0 = src[(size_t)c0 * 16 + sub];
        uint2 u1 = src[(size_t)c1 * 16 + sub];
        uint2 u2 = src[(size_t)c2 * 16 + sub];
        uint2 u3 = src[(size_t)c3 * 16 + sub];
        float4 v0 = h4_to_f4(u0);
        float4 v1 = h4_to_f4(u1);
        float4 v2 = h4_to_f4(u2);
        float4 v3 = h4_to_f4(u3);
        float4 s01, s23;
        s01.x = v0.x + v1.x; s01.y = v0.y + v1.y;
        s01.z = v0.z + v1.z; s01.w = v0.w + v1.w;
        s23.x = v2.x + v3.x; s23.y = v2.y + v3.y;
        s23.z = v2.z + v3.z; s23.w = v2.w + v3.w;
        acc.x += s01.x + s23.x; acc.y += s01.y + s23.y;
        acc.z += s01.z + s23.z; acc.w += s01.w + s23.w;
    }
    for (; j < e0; j++) {
        float4 v = h4_to_f4(src[(size_t)g_csr[j] * 16 + sub]);
        acc.x += v.x; acc.y += v.y; acc.z += v.z; acc.w += v.w;
    }
    if (node < n) {
        float d = g_dinv[node];
        float4 o;
        o.x = acc.x * d; o.y = acc.y * d; o.z = acc.z * d; o.w = acc.w * d;
        *(float4*)(g_agg + (size_t)node * C + (sub << 2)) = o;
    }
}

// ---------------- GEMM: relu( concat(X, AGG)[n,128] @ W^T + b ) -------------
// Tile: 128 nodes x 64 cols per block, 128 threads, k chunked by 32.
// 8x8 per-thread tile via packed f32x2 FFMA, register-pipelined chunks.
// X-half source: srcSel 0 -> fp32 input x; srcSel 1 -> fp16 g_h1h (converted
// during staging). AGG half always fp32 g_agg.
// fuseMode 0: write ONLY the fp16 mirror g_h1h (h1's sole copy).
// fuseMode 1: layer-3 fusion (project onto W3 halves, emit g_s/g_p scalars).
#define NT2 128
#define KC  32

__global__ __launch_bounds__(128, 4) void k_gemm(
    const float* __restrict__ Xin, int srcSel,
    const float* __restrict__ W, const float* __restrict__ B,
    int n, int do_relu, int fuseMode, const float* __restrict__ W3)
{
    __shared__ float Hs[KC][NT2];      // transposed H chunk: Hs[kk][node]
    __shared__ float Wd[KC][128];      // duplicated W chunk

    int t  = threadIdx.x;              // 0..127
    int nb = blockIdx.x * NT2;
    int tx = t & 15;      // node-group: 16 groups x 8 nodes
    int ty = t >> 4;      // col-group:   8 groups x 8 cols

    unsigned long long acc[4][8];
    #pragma unroll
    for (int i = 0; i < 4; i++)
        #pragma unroll
        for (int j = 0; j < 8; j++) acc[i][j] = 0ull;

    int nglob = nb + t;          // H staging: one node per thread
    int colw  = t >> 1;          // W staging: col 0..63
    int q     = t & 1;           // half of the 32-k chunk (16 k each)

    float4 hreg[8];
    float4 wreg[4];

    // X-half loader: chunk columns koff..koff+31 of node nglob's 64-wide row.
    auto load_x_chunk = [&](int koff) {
        if (srcSel == 0) {
            const float4* srow = (const float4*)(Xin + (size_t)nglob * C + koff);
            #pragma unroll
            for (int i = 0; i < 8; i++)
                hreg[i] = (nglob < n) ? srow[i] : make_float4(0.f, 0.f, 0.f, 0.f);
        } else {
            const uint2* hrow = (const uint2*)(g_h1h + (size_t)nglob * C + koff);
            #pragma unroll
            for (int i = 0; i < 8; i++)
                hreg[i] = (nglob < n) ? h4_to_f4(hrow[i])
                                      : make_float4(0.f, 0.f, 0.f, 0.f);
        }
    };

    // preload chunk 0
    load_x_chunk(0);
    #pragma unroll
    for (int i = 0; i < 4; i++)
        wreg[i] = *(const float4*)(W + colw * 128 + q * 16 + i * 4);

    for (int c = 0; c < 4; c++) {
        #pragma unroll
        for (int i = 0; i < 8; i++) {
            int kk = i * 4;
            Hs[kk + 0][t] = hreg[i].x;
            Hs[kk + 1][t] = hreg[i].y;
            Hs[kk + 2][t] = hreg[i].z;
            Hs[kk + 3][t] = hreg[i].w;
        }
        #pragma unroll
        for (int i = 0; i < 4; i++) {
            int kk = q * 16 + i * 4;
            Wd[kk + 0][2 * colw] = wreg[i].x;  Wd[kk + 0][2 * colw + 1] = wreg[i].x;
            Wd[kk + 1][2 * colw] = wreg[i].y;  Wd[kk + 1][2 * colw + 1] = wreg[i].y;
            Wd[kk + 2][2 * colw] = wreg[i].z;  Wd[kk + 2][2 * colw + 1] = wreg[i].z;
            Wd[kk + 3][2 * colw] = wreg[i].w;  Wd[kk + 3][2 * colw + 1] = wreg[i].w;
        }
        __syncthreads();

        if (c < 3) {
            int cn = c + 1;
            int kb = cn * 32;
            if (cn < 2) {
                load_x_chunk((cn & 1) * 32);
            } else {
                const float4* srow =
                    (const float4*)(g_agg + (size_t)nglob * C + (cn & 1) * 32);
                #pragma unroll
                for (int i = 0; i < 8; i++)
                    hreg[i] = (nglob < n) ? srow[i]
                                          : make_float4(0.f, 0.f, 0.f, 0.f);
            }
            #pragma unroll
            for (int i = 0; i < 4; i++)
                wreg[i] = *(const float4*)(W + colw * 128 + kb + q * 16 + i * 4);
        }

        #pragma unroll 8
        for (int kk = 0; kk < KC; kk++) {
            ulonglong2 aA = *(const ulonglong2*)&Hs[kk][tx * 8];
            ulonglong2 aB = *(const ulonglong2*)&Hs[kk][tx * 8 + 4];
            const ulonglong2* bp = (const ulonglong2*)&Wd[kk][ty * 16];
            ulonglong2 b01 = bp[0], b23 = bp[1], b45 = bp[2], b67 = bp[3];
            unsigned long long bb[8] = {b01.x, b01.y, b23.x, b23.y,
                                        b45.x, b45.y, b67.x, b67.y};
            #pragma unroll
            for (int j = 0; j < 8; j++) {
                FMA2(acc[0][j], aA.x, bb[j]);
                FMA2(acc[1][j], aA.y, bb[j]);
                FMA2(acc[2][j], aB.x, bb[j]);
                FMA2(acc[3][j], aB.y, bb[j]);
            }
        }
        __syncthreads();
    }

    float4 bb0 = *(const float4*)(B + ty * 8);
    float4 bb1 = *(const float4*)(B + ty * 8 + 4);
    float bias[8] = {bb0.x, bb0.y, bb0.z, bb0.w, bb1.x, bb1.y, bb1.z, bb1.w};

    if (fuseMode == 0) {
        // epilogue: write ONLY the fp16 copy of h1
        #pragma unroll
        for (int i2 = 0; i2 < 4; i2++) {
            float lo[8], hi[8];
            #pragma unroll
            for (int j = 0; j < 8; j++) {
                UNPACK2(lo[j], hi[j], acc[i2][j]);
                lo[j] += bias[j]; hi[j] += bias[j];
                if (do_relu) { lo[j] = fmaxf(lo[j], 0.f); hi[j] = fmaxf(hi[j], 0.f); }
            }
            int n0 = nb + tx * 8 + i2 * 2;
            if (n0 < n) {
                __half2 p0 = __floats2half2_rn(lo[0], lo[1]);
                __half2 p1 = __floats2half2_rn(lo[2], lo[3]);
                __half2 p2 = __floats2half2_rn(lo[4], lo[5]);
                __half2 p3 = __floats2half2_rn(lo[6], lo[7]);
                *(uint4*)(g_h1h + (size_t)n0 * C + ty * 8) =
                    make_uint4(*(unsigned*)&p0, *(unsigned*)&p1,
                               *(unsigned*)&p2, *(unsigned*)&p3);
            }
            if (n0 + 1 < n) {
                __half2 p0 = __floats2half2_rn(hi[0], hi[1]);
                __half2 p1 = __floats2half2_rn(hi[2], hi[3]);
                __half2 p2 = __floats2half2_rn(hi[4], hi[5]);
                __half2 p3 = __floats2half2_rn(hi[6], hi[7]);
                *(uint4*)(g_h1h + (size_t)(n0 + 1) * C + ty * 8) =
                    make_uint4(*(unsigned*)&p0, *(unsigned*)&p1,
                               *(unsigned*)&p2, *(unsigned*)&p3);
            }
        }
    } else {
        float w3s[8], w3p[8];
        #pragma unroll
        for (int j = 0; j < 8; j++) {
            w3s[j] = W3[ty * 8 + j];
            w3p[j] = W3[64 + ty * 8 + j];
        }
        float* Ps = &Hs[0][0];          // [8][128]
        float* Ss = &Hs[0][0] + 1024;   // [8][128]

        #pragma unroll
        for (int i2 = 0; i2 < 4; i2++) {
            float lo[8], hi[8];
            float slo = 0.f, plo = 0.f, shi = 0.f, phi = 0.f;
            #pragma unroll
            for (int j = 0; j < 8; j++) {
                UNPACK2(lo[j], hi[j], acc[i2][j]);
                lo[j] = fmaxf(lo[j] + bias[j], 0.f);
                hi[j] = fmaxf(hi[j] + bias[j], 0.f);
                slo += lo[j] * w3s[j];  plo += lo[j] * w3p[j];
                shi += hi[j] * w3s[j];  phi += hi[j] * w3p[j];
            }
            int nl = tx * 8 + i2 * 2;
            Ss[ty * 128 + nl]     = slo;  Ps[ty * 128 + nl]     = plo;
            Ss[ty * 128 + nl + 1] = shi;  Ps[ty * 128 + nl + 1] = phi;
        }
        __syncthreads();
        int node = nb + t;
        if (node < n) {
            float s = 0.f, p = 0.f;
            #pragma unroll
            for (int g = 0; g < 8; g++) {
                s += Ss[g * 128 + t];
                p += Ps[g * 128 + t];
            }
            g_agg[MAXN + node] = s;   // g_s (bias b3 added in k_out)
            g_agg[node]        = p;   // g_p
        }
    }
}

// scalar aggregation + combine: out[i] = s[i] + b3 + dinv[i] * sum p[nbrs].
// Tail also resets g_count/g_blkagg for the next replay (consumed only by
// k_hist/k_scan, which run before this kernel in every invocation).
__global__ void k_out(float* __restrict__ OUT, const float* __restrict__ B3, int n) {
    int i = blockIdx.x * blockDim.x + threadIdx.x;
    if (i < MAXBLK) g_blkagg[i] = 0;
    if (i >= n) return;
    g_count[i] = 0;
    int s = g_off[i], e = g_off[i + 1];
    float a0 = 0.f, a1 = 0.f, a2 = 0.f, a3 = 0.f;
    float a4 = 0.f, a5 = 0.f, a6 = 0.f, a7 = 0.f;
    int j = s;
    for (; j + 7 < e; j += 8) {
        a0 += g_agg[g_csr[j]];
        a1 += g_agg[g_csr[j + 1]];
        a2 += g_agg[g_csr[j + 2]];
        a3 += g_agg[g_csr[j + 3]];
        a4 += g_agg[g_csr[j + 4]];
        a5 += g_agg[g_csr[j + 5]];
        a6 += g_agg[g_csr[j + 6]];
        a7 += g_agg[g_csr[j + 7]];
    }
    for (; j < e; j++) a0 += g_agg[g_csr[j]];
    float acc = ((a0 + a1) + (a2 + a3)) + ((a4 + a5) + (a6 + a7));
    OUT[i] = g_agg[MAXN + i] + B3[0] + acc * g_dinv[i];
}

// ---------------- driver ----------------------------------------------------
extern "C" void kernel_launch(void* const* d_in, const int* in_sizes, int n_in,
                              void* d_out, int out_size)
{
    const float* x  = (const float*)d_in[0];
    const int*   ei = (const int*)  d_in[1];
    const float* W1 = (const float*)d_in[2];
    const float* b1 = (const float*)d_in[3];
    const float* W2 = (const float*)d_in[4];
    const float* b2 = (const float*)d_in[5];
    const float* W3 = (const float*)d_in[6];
    const float* b3 = (const float*)d_in[7];
    float* out = (float*)d_out;

    int n = in_sizes[0] / C;     // 100000
    int e = in_sizes[1] / 2;     // 1600000
    const int* row = ei;
    const int* col = ei + e;

    int scanBlk = (n + SCANB - 1) / SCANB;   // 391 <= MAXBLK

    // CSR build + x->fp16 (fused), 3 launches; counter resets in k_out tail
    k_hist<<<(e + 255) / 256, 256>>>(row, e, x, n * 16);   // launch 0
    k_scan<<<scanBlk, SCANB>>>(n, e);                      // launch 1
    k_fill<<<(e + 255) / 256, 256>>>(row, col, e);         // launch 2

    int aggBlocks  = ((n + 1) / 2 + 7) / 8;  // 2 nodes/warp, 8 warps/block
    int gemmBlocks = (n + NT2 - 1) / NT2;    // 782
    int tpnBlocks  = (n + 255) / 256;

    // layer 1: x -> h1 (fp16 only)
    k_agg <<<aggBlocks, 256>>>(0, n);                      // launch 3
    k_gemm<<<gemmBlocks, 128>>>(x, 0, W1, b1, n, 1, 0, nullptr);   // launch 4
    // layer 2 + 3: h1(fp16) -> (s,p) scalars (h2 never materialized)
    k_agg <<<aggBlocks, 256>>>(1, n);                      // launch 5
    k_gemm<<<gemmBlocks, 128>>>(nullptr, 1, W2, b2, n, 1, 1, W3);  // launch 6
    // layer 3 scalar aggregation (+ counter resets for next replay)
    k_out <<<tpnBlocks, 256>>>(out, b3, n);                // launch 7
}